// round 15
// baseline (speedup 1.0000x reference)
#include <cuda_runtime.h>
#include <math.h>

#define TT 512
#define BB 32
#define HH 512
#define GG 2048
#define NIN 64
#define NB 128
#define HB 16384   // HH*BB
#define GB 65536   // GG*BB

typedef unsigned long long u64;

// ---- static device scratch (no allocations allowed) ----
__device__ float g_xg0[(size_t)TT * GB];   // xg0 -> activated gates L0 -> dg0 (in place)
__device__ float g_xg1[(size_t)TT * GB];
__device__ float g_c0[(size_t)TT * HB];
__device__ float g_c1[(size_t)TT * HB];
__device__ float g_h0[(size_t)TT * HB];    // [t][k][b]  (layer0 h, consumed by k_xg1)
__device__ float g_hT[(size_t)TT * HB];    // [t][b][j]  (transposed h for fwd staging)
__device__ float g_dx1[(size_t)TT * HB];   // dL/d(h0) from layer1 input path, [t][j][b]

__device__ volatile unsigned g_flags[128];

// single-hop distributed grid barrier: each CTA publishes its own flag,
// every CTA polls all 128 flags with warp 0. No central atomic serialization.
__device__ __forceinline__ void grid_barrier(unsigned target) {
    __syncthreads();
    if (threadIdx.x == 0) {
        __threadfence();
        g_flags[blockIdx.x] = target;
    }
    if (threadIdx.x < 32) {
        bool ok;
        do {
            unsigned v0 = g_flags[threadIdx.x * 4 + 0];
            unsigned v1 = g_flags[threadIdx.x * 4 + 1];
            unsigned v2 = g_flags[threadIdx.x * 4 + 2];
            unsigned v3 = g_flags[threadIdx.x * 4 + 3];
            ok = ((int)(v0 - target) >= 0) & ((int)(v1 - target) >= 0) &
                 ((int)(v2 - target) >= 0) & ((int)(v3 - target) >= 0);
        } while (!__all_sync(0xffffffffu, ok));
        __threadfence();
    }
    __syncthreads();
}

__device__ __forceinline__ float sigf(float x) { return 1.0f / (1.0f + expf(-x)); }

// ---- packed fp32x2 helpers ----
__device__ __forceinline__ u64 pack2(float x, float y) {
    u64 r; asm("mov.b64 %0, {%1, %2};" : "=l"(r) : "f"(x), "f"(y)); return r;
}
__device__ __forceinline__ void unpack2(u64 v, float& x, float& y) {
    asm("mov.b64 {%0, %1}, %2;" : "=f"(x), "=f"(y) : "l"(v));
}
__device__ __forceinline__ u64 ffma2(u64 a, u64 b, u64 c) {
    u64 d; asm("fma.rn.f32x2 %0, %1, %2, %3;" : "=l"(d) : "l"(a), "l"(b), "l"(c)); return d;
}

// ================= K1: xg0 = x @ W_ih0^T + b_ih0 + b_hh0, layout [t][n][b] =================
__global__ void __launch_bounds__(256) k_xg0(const float* __restrict__ x,
                                             const float* __restrict__ Wih,
                                             const float* __restrict__ bih,
                                             const float* __restrict__ bhh) {
    __shared__ float xs[32 * 65];
    __shared__ float Ws[128 * 64];
    const int tid = threadIdx.x, t = blockIdx.y, n0 = blockIdx.x * 128;
    for (int i = tid; i < 32 * 64; i += 256) {
        int b = i >> 6, k = i & 63;
        xs[b * 65 + k] = x[((size_t)b * TT + t) * NIN + k];
    }
    for (int i = tid; i < 128 * 64; i += 256) {
        int r = i >> 6, k = i & 63;
        Ws[i] = Wih[(size_t)(n0 + r) * NIN + k];
    }
    __syncthreads();
    const int b = tid & 31, ng = tid >> 5;
    u64 acc[16];
#pragma unroll
    for (int m = 0; m < 16; ++m) acc[m] = 0ull;
    for (int k = 0; k < 64; k += 4) {
        u64 hp01 = pack2(xs[b * 65 + k], xs[b * 65 + k + 1]);
        u64 hp23 = pack2(xs[b * 65 + k + 2], xs[b * 65 + k + 3]);
#pragma unroll
        for (int m = 0; m < 16; ++m) {
            ulonglong2 wp = *(const ulonglong2*)&Ws[(ng * 16 + m) * 64 + k];
            acc[m] = ffma2(wp.x, hp01, acc[m]);
            acc[m] = ffma2(wp.y, hp23, acc[m]);
        }
    }
    size_t tg = (size_t)t * GB;
#pragma unroll
    for (int m = 0; m < 16; ++m) {
        int n = n0 + ng * 16 + m;
        float lo, hi; unpack2(acc[m], lo, hi);
        g_xg0[tg + (size_t)n * BB + b] = lo + hi + bih[n] + bhh[n];
    }
}

// ================= K2: xg1 = h0 @ W_ih1^T + biases =================
__global__ void __launch_bounds__(256) k_xg1(const float* __restrict__ Wih,
                                             const float* __restrict__ bih,
                                             const float* __restrict__ bhh) {
    __shared__ float hs[64 * 32];
    __shared__ float Ws[64 * 64];
    const int tid = threadIdx.x, t = blockIdx.y, n0 = blockIdx.x * 64;
    const int b = tid & 31, ng = tid >> 5;
    u64 acc[8];
#pragma unroll
    for (int m = 0; m < 8; ++m) acc[m] = 0ull;
    for (int kc = 0; kc < HH; kc += 64) {
        for (int i = tid; i < 64 * 32; i += 256)
            hs[i] = g_h0[(size_t)t * HB + (size_t)kc * BB + i];
        for (int i = tid; i < 64 * 64; i += 256) {
            int r = i >> 6, k = i & 63;
            Ws[i] = Wih[(size_t)(n0 + r) * HH + kc + k];
        }
        __syncthreads();
        for (int k = 0; k < 64; k += 4) {
            u64 hp01 = pack2(hs[(k + 0) * 32 + b], hs[(k + 1) * 32 + b]);
            u64 hp23 = pack2(hs[(k + 2) * 32 + b], hs[(k + 3) * 32 + b]);
#pragma unroll
            for (int m = 0; m < 8; ++m) {
                ulonglong2 wp = *(const ulonglong2*)&Ws[(ng * 8 + m) * 64 + k];
                acc[m] = ffma2(wp.x, hp01, acc[m]);
                acc[m] = ffma2(wp.y, hp23, acc[m]);
            }
        }
        __syncthreads();
    }
    size_t tg = (size_t)t * GB;
#pragma unroll
    for (int m = 0; m < 8; ++m) {
        int n = n0 + ng * 8 + m;
        float lo, hi; unpack2(acc[m], lo, hi);
        g_xg1[tg + (size_t)n * BB + b] = lo + hi + bih[n] + bhh[n];
    }
}

// ================= K3: dx1[t][k][b] = sum_n dg1[t][n][b] * W_ih1[n][k] =================
__global__ void __launch_bounds__(256) k_dx1(const float* __restrict__ Wih) {
    __shared__ float dgs[64 * 32];
    __shared__ float Ws[64 * 64];
    const int tid = threadIdx.x, t = blockIdx.y, kt0 = blockIdx.x * 64;
    const int b = tid & 31, kg = tid >> 5;
    u64 acc[4];
#pragma unroll
    for (int m = 0; m < 4; ++m) acc[m] = 0ull;
    for (int nb = 0; nb < GG; nb += 64) {
        for (int i = tid; i < 64 * 32; i += 256)
            dgs[i] = g_xg1[(size_t)t * GB + (size_t)nb * BB + i];
        for (int i = tid; i < 64 * 64; i += 256) {
            int r = i >> 6, k = i & 63;
            Ws[i] = Wih[(size_t)(nb + r) * HH + kt0 + k];
        }
        __syncthreads();
        for (int n = 0; n < 64; ++n) {
            u64 dpp = pack2(dgs[n * 32 + b], dgs[n * 32 + b]);
            ulonglong2 wa = *(const ulonglong2*)&Ws[n * 64 + kg * 8];
            ulonglong2 wb = *(const ulonglong2*)&Ws[n * 64 + kg * 8 + 4];
            acc[0] = ffma2(wa.x, dpp, acc[0]);
            acc[1] = ffma2(wa.y, dpp, acc[1]);
            acc[2] = ffma2(wb.x, dpp, acc[2]);
            acc[3] = ffma2(wb.y, dpp, acc[3]);
        }
        __syncthreads();
    }
#pragma unroll
    for (int p = 0; p < 4; ++p) {
        float lo, hi; unpack2(acc[p], lo, hi);
        g_dx1[(size_t)t * HB + (size_t)(kt0 + kg * 8 + 2 * p) * BB + b] = lo;
        g_dx1[(size_t)t * HB + (size_t)(kt0 + kg * 8 + 2 * p + 1) * BB + b] = hi;
    }
}

// ================= K4: out[b][t][k] = sum_n dg0[t][n][b] * W_ih0[n][k], k<64 =================
__global__ void __launch_bounds__(256) k_dx(const float* __restrict__ Wih,
                                            float* __restrict__ out) {
    __shared__ float dgs[64 * 32];
    __shared__ float Ws[64 * 64];
    const int tid = threadIdx.x, t = blockIdx.x;
    const int b = tid & 31, kg = tid >> 5;
    u64 acc[4];
#pragma unroll
    for (int m = 0; m < 4; ++m) acc[m] = 0ull;
    for (int nb = 0; nb < GG; nb += 64) {
        for (int i = tid; i < 64 * 32; i += 256)
            dgs[i] = g_xg0[(size_t)t * GB + (size_t)nb * BB + i];
        for (int i = tid; i < 64 * 64; i += 256) {
            int r = i >> 6, k = i & 63;
            Ws[i] = Wih[(size_t)(nb + r) * NIN + k];
        }
        __syncthreads();
        for (int n = 0; n < 64; ++n) {
            u64 dpp = pack2(dgs[n * 32 + b], dgs[n * 32 + b]);
            ulonglong2 wa = *(const ulonglong2*)&Ws[n * 64 + kg * 8];
            ulonglong2 wb = *(const ulonglong2*)&Ws[n * 64 + kg * 8 + 4];
            acc[0] = ffma2(wa.x, dpp, acc[0]);
            acc[1] = ffma2(wa.y, dpp, acc[1]);
            acc[2] = ffma2(wb.x, dpp, acc[2]);
            acc[3] = ffma2(wb.y, dpp, acc[3]);
        }
        __syncthreads();
    }
#pragma unroll
    for (int p = 0; p < 4; ++p) {
        float lo, hi; unpack2(acc[p], lo, hi);
        out[((size_t)b * TT + t) * NIN + kg * 8 + 2 * p] = lo;
        out[((size_t)b * TT + t) * NIN + kg * 8 + 2 * p + 1] = hi;
    }
}

// ================= persistent LSTM forward (512 threads/CTA) =================
// CTA owns 4 h-columns (j0..j0+3) -> 16 gate rows.
// 16 warps = 2 row-groups (8 rows) x 8 k-eighths (64 k).
// h_{t-1} staged as u64 pairs with XOR swizzle -> conflict-free LDS.64 reads.
// smem: sW 32KB | shq 64KB | sred 16KB | sact 2KB = 114KB
#define FWD_SMEM ((8192 + 16384 + 4096 + 512) * 4)
__global__ void __launch_bounds__(512, 1) lstm_fwd_kernel(const float* __restrict__ Whh,
                                                          int layer) {
    extern __shared__ float smem[];
    float* sW = smem;                          // [16][512]
    u64* shq = (u64*)(smem + 8192);            // [32][256] u64, swizzled
    float* sred = smem + 8192 + 16384;         // [8][512]
    float* sact = sred + 4096;                 // [512]

    float* gates = layer ? g_xg1 : g_xg0;
    float* cbuf = layer ? g_c1 : g_c0;

    const int tid = threadIdx.x, j0 = blockIdx.x * 4;
    const int b = tid & 31, wid = tid >> 5;
    const int rg = wid & 1, kh = wid >> 1;     // 2 row-groups x 8 k-eighths
    const int q_rho = tid >> 5, q_bb = tid & 31;
    const int q_n = (q_rho >> 2) * HH + j0 + (q_rho & 3);

    for (int i = tid; i < 16 * 512; i += 512) {
        int r = i >> 9, k = i & 511;
        int n = (r >> 2) * HH + j0 + (r & 3);
        sW[i] = Whh[(size_t)n * HH + k];
    }
    unsigned gen0 = g_flags[blockIdx.x];
    float creg = 0.f;
    __syncthreads();

    for (int t = 0; t < TT; ++t) {
        size_t tg = (size_t)t * GB;
        float pre_xg = gates[tg + (size_t)q_n * BB + q_bb];

        // stage h_{t-1} into swizzled u64 buffer shq[b][k2 ^ (b&15)]
        if (t == 0) {
#pragma unroll
            for (int r = 0; r < 16; ++r) shq[tid + r * 512] = 0ull;
        } else {
            const float* src = g_hT + (size_t)(t - 1) * HB;   // [b][j]
#pragma unroll
            for (int r = 0; r < 8; ++r) {
                int i4 = tid + r * 512;
                float4 v = *(const float4*)&src[i4 * 4];
                int bb = i4 >> 7;
                int k2 = (i4 & 127) * 2;
                int s = bb & 15;
                u64* dst = shq + bb * 256;
                dst[k2 ^ s] = pack2(v.x, v.y);
                dst[(k2 + 1) ^ s] = pack2(v.z, v.w);
            }
        }
        __syncthreads();

        // matmul: 8 rows (rg), 64 k (kh), lane b
        u64 acc[8];
#pragma unroll
        for (int m = 0; m < 8; ++m) acc[m] = 0ull;
        const int s = b & 15;
        const u64* hq = shq + b * 256;
        const float* wp = sW + (rg * 8) * 512;
        const int kb = kh * 64;
#pragma unroll 4
        for (int k = kb; k < kb + 64; k += 4) {
            int k2 = k >> 1;
            u64 h01 = hq[k2 ^ s];
            u64 h23 = hq[(k2 + 1) ^ s];
#pragma unroll
            for (int m = 0; m < 8; ++m) {
                ulonglong2 w = *(const ulonglong2*)&wp[m * 512 + k];
                acc[m] = ffma2(w.x, h01, acc[m]);
                acc[m] = ffma2(w.y, h23, acc[m]);
            }
        }
#pragma unroll
        for (int m = 0; m < 8; ++m) {
            float lo, hi; unpack2(acc[m], lo, hi);
            sred[kh * 512 + (rg * 8 + m) * 32 + b] = lo + hi;
        }
        __syncthreads();

        // phase B: one gate value per thread
        {
            float g = pre_xg;
#pragma unroll
            for (int p = 0; p < 8; ++p) g += sred[p * 512 + tid];
            float v = (q_rho >= 8 && q_rho < 12) ? tanhf(g) : sigf(g);
            sact[tid] = v;
            gates[tg + (size_t)q_n * BB + q_bb] = v;
        }
        __syncthreads();

        // phase C: c/h update (tid<128)
        if (tid < 128) {
            int jl = tid >> 5, bb = tid & 31;
            float iv = sact[(0 + jl) * 32 + bb];
            float fv = sact[(4 + jl) * 32 + bb];
            float gv = sact[(8 + jl) * 32 + bb];
            float ov = sact[(12 + jl) * 32 + bb];
            float c = fv * creg + iv * gv;
            creg = c;
            float h = ov * tanhf(c);
            int j = j0 + jl;
            cbuf[(size_t)t * HB + (size_t)j * BB + bb] = c;
            g_hT[(size_t)t * HB + (size_t)bb * HH + j] = h;
            if (layer == 0)
                g_h0[(size_t)t * HB + (size_t)j * BB + bb] = h;
        }
        grid_barrier(gen0 + (unsigned)(t + 1));
    }
}

// ================= persistent LSTM backward (512 threads/CTA) =================
// CTA owns 16 j x 8 b. W_hh column slice 128KB resident in smem; dg staged 64KB/step.
// smem: sWc[2048][16] 128KB | sdg[2048][8] 64KB | sred[16][128] 8KB = 200KB
#define BWD_SMEM ((2048 * 16 + 2048 * 8 + 2048) * 4)
__global__ void __launch_bounds__(512, 1) lstm_bwd_kernel(const float* __restrict__ Whh,
                                                          const float* __restrict__ Wout,
                                                          int layer) {
    extern __shared__ float smem[];
    float* sWc = smem;                    // [n][16 j]
    float* sdg = smem + 2048 * 16;        // [n][8 b]
    float* sred = sdg + 2048 * 8;         // [16 warps][16 j * 8 b]

    float* gates = layer ? g_xg1 : g_xg0;
    const float* cbuf = layer ? g_c1 : g_c0;

    const int tid = threadIdx.x;
    const int j0 = (blockIdx.x >> 2) * 16;
    const int b0 = (blockIdx.x & 3) * 8;
    const int wid = tid >> 5, lane = tid & 31;
    const int bL = lane & 7, jh = lane >> 3;        // lane: 8 b x 4 j-quads
    const int cj = tid >> 3, cb = tid & 7;          // phase-C (tid<128): 16 j x 8 b

    // sWc[n][jj] = Whh[n][j0+jj]
    for (int i = tid; i < 2048 * 4; i += 512) {
        int n = i >> 2, q = i & 3;
        *(float4*)&sWc[n * 16 + q * 4] = *(const float4*)&Whh[(size_t)n * HH + j0 + q * 4];
    }
    unsigned gen0 = g_flags[blockIdx.x];
    float dcreg = 0.f;
    float dho_c = 0.f;
    if (layer == 1 && tid < 128) dho_c = Wout[j0 + cj];
    __syncthreads();

    for (int t = TT - 1; t >= 0; --t) {
        // prefetch all barrier-independent operands (tid<128)
        float p_iv = 0.f, p_fv = 0.f, p_gv = 0.f, p_ov = 0.f;
        float p_c = 0.f, p_cprev = 0.f, p_dho = 0.f;
        size_t gb = 0;
        if (tid < 128) {
            int j = j0 + cj, b = b0 + cb;
            gb = (size_t)t * GB + (size_t)j * BB + b;
            size_t co = (size_t)t * HB + (size_t)j * BB + b;
            p_iv = gates[gb];
            p_fv = gates[gb + (size_t)512 * BB];
            p_gv = gates[gb + (size_t)1024 * BB];
            p_ov = gates[gb + (size_t)1536 * BB];
            p_c = cbuf[co];
            p_cprev = (t > 0) ? cbuf[co - HB] : 0.f;
            p_dho = (layer == 1) ? dho_c : g_dx1[co];
        }

        u64 a01 = 0ull, a23 = 0ull;
        if (t < TT - 1) {
            // stage dg[t+1][n][b0..b0+7]: 4096 float4, 8 per thread
            const float* dgp = gates + (size_t)(t + 1) * GB;
#pragma unroll
            for (int r = 0; r < 8; ++r) {
                int i4 = tid + r * 512;
                int n = i4 >> 1, bq = i4 & 1;
                *(float4*)&sdg[n * 8 + bq * 4] =
                    *(const float4*)&dgp[(size_t)n * BB + b0 + bq * 4];
            }
            __syncthreads();
            const int nbeg = wid * 128;
#pragma unroll 8
            for (int n = nbeg; n < nbeg + 128; ++n) {
                float dgv = sdg[n * 8 + bL];
                u64 dpp = pack2(dgv, dgv);
                ulonglong2 w = *(const ulonglong2*)&sWc[n * 16 + jh * 4];
                a01 = ffma2(w.x, dpp, a01);
                a23 = ffma2(w.y, dpp, a23);
            }
        }
        {
            float lo, hi;
            unpack2(a01, lo, hi);
            sred[wid * 128 + (jh * 4 + 0) * 8 + bL] = lo;
            sred[wid * 128 + (jh * 4 + 1) * 8 + bL] = hi;
            unpack2(a23, lo, hi);
            sred[wid * 128 + (jh * 4 + 2) * 8 + bL] = lo;
            sred[wid * 128 + (jh * 4 + 3) * 8 + bL] = hi;
        }
        __syncthreads();

        if (tid < 128) {
            float dhrec = 0.f;
#pragma unroll
            for (int h = 0; h < 16; ++h) dhrec += sred[h * 128 + tid];
            float dh = p_dho + dhrec;
            float tc = tanhf(p_c);
            float dc = dcreg + dh * p_ov * (1.f - tc * tc);
            float dgi = (dc * p_gv) * p_iv * (1.f - p_iv);
            float dgf = (dc * p_cprev) * p_fv * (1.f - p_fv);
            float dgg = (dc * p_iv) * (1.f - p_gv * p_gv);
            float dgo = (dh * tc) * p_ov * (1.f - p_ov);
            dcreg = dc * p_fv;
            gates[gb] = dgi;
            gates[gb + (size_t)512 * BB] = dgf;
            gates[gb + (size_t)1024 * BB] = dgg;
            gates[gb + (size_t)1536 * BB] = dgo;
        }
        grid_barrier(gen0 + (unsigned)(TT - t));
    }
}

extern "C" void kernel_launch(void* const* d_in, const int* in_sizes, int n_in,
                              void* d_out, int out_size) {
    const float* x    = (const float*)d_in[0];
    const float* Wih0 = (const float*)d_in[1];
    const float* Whh0 = (const float*)d_in[2];
    const float* bih0 = (const float*)d_in[3];
    const float* bhh0 = (const float*)d_in[4];
    const float* Wih1 = (const float*)d_in[5];
    const float* Whh1 = (const float*)d_in[6];
    const float* bih1 = (const float*)d_in[7];
    const float* bhh1 = (const float*)d_in[8];
    const float* Wout = (const float*)d_in[9];
    float* out = (float*)d_out;

    cudaFuncSetAttribute(lstm_fwd_kernel, cudaFuncAttributeMaxDynamicSharedMemorySize, FWD_SMEM);
    cudaFuncSetAttribute(lstm_bwd_kernel, cudaFuncAttributeMaxDynamicSharedMemorySize, BWD_SMEM);

    k_xg0<<<dim3(16, 512), 256>>>(x, Wih0, bih0, bhh0);
    lstm_fwd_kernel<<<NB, 512, FWD_SMEM>>>(Whh0, 0);
    k_xg1<<<dim3(32, 512), 256>>>(Wih1, bih1, bhh1);
    lstm_fwd_kernel<<<NB, 512, FWD_SMEM>>>(Whh1, 1);
    lstm_bwd_kernel<<<NB, 512, BWD_SMEM>>>(Whh1, Wout, 1);
    k_dx1<<<dim3(8, 512), 256>>>(Wih1);
    lstm_bwd_kernel<<<NB, 512, BWD_SMEM>>>(Whh0, Wout, 0);
    k_dx<<<512, 256>>>(Wih0, out);
}

// round 16
// speedup vs baseline: 1.8170x; 1.8170x over previous
#include <cuda_runtime.h>
#include <math.h>

#define TT 512
#define BB 32
#define HH 512
#define GG 2048
#define NIN 64
#define NB 128
#define HB 16384   // HH*BB
#define GB 65536   // GG*BB

typedef unsigned long long u64;

// ---- static device scratch (no allocations allowed) ----
__device__ float g_xg0[(size_t)TT * GB];   // xg0 -> activated gates L0 -> dg0 (in place)
__device__ float g_xg1[(size_t)TT * GB];
__device__ float g_c0[(size_t)TT * HB];
__device__ float g_c1[(size_t)TT * HB];
__device__ float g_h0[(size_t)TT * HB];    // [t][k][b]  (layer0 h, consumed by k_xg1)
__device__ float g_hT[(size_t)TT * HB];    // [t][b][j]  (transposed h for fwd staging)
__device__ float g_dx1[(size_t)TT * HB];   // dL/d(h0) from layer1 input path, [t][j][b]

__device__ unsigned g_bar_count = 0;
__device__ unsigned g_bar_gen   = 0;

// central-atomic grid barrier (R14 version — proven fast)
__device__ __forceinline__ void grid_barrier(unsigned target) {
    __syncthreads();
    if (threadIdx.x == 0) {
        __threadfence();
        unsigned old = atomicAdd(&g_bar_count, 1u);
        if (old == NB - 1) {
            g_bar_count = 0;
            __threadfence();
            atomicExch(&g_bar_gen, target);
        } else {
            while ((int)(*(volatile unsigned*)&g_bar_gen - target) < 0) {}
            __threadfence();
        }
    }
    __syncthreads();
}

__device__ __forceinline__ float sigf(float x) { return 1.0f / (1.0f + expf(-x)); }

// ---- packed fp32x2 helpers ----
__device__ __forceinline__ u64 pack2(float x, float y) {
    u64 r; asm("mov.b64 %0, {%1, %2};" : "=l"(r) : "f"(x), "f"(y)); return r;
}
__device__ __forceinline__ void unpack2(u64 v, float& x, float& y) {
    asm("mov.b64 {%0, %1}, %2;" : "=f"(x), "=f"(y) : "l"(v));
}
__device__ __forceinline__ u64 ffma2(u64 a, u64 b, u64 c) {
    u64 d; asm("fma.rn.f32x2 %0, %1, %2, %3;" : "=l"(d) : "l"(a), "l"(b), "l"(c)); return d;
}

// ================= K1: xg0 = x @ W_ih0^T + b_ih0 + b_hh0, layout [t][n][b] =================
__global__ void __launch_bounds__(256) k_xg0(const float* __restrict__ x,
                                             const float* __restrict__ Wih,
                                             const float* __restrict__ bih,
                                             const float* __restrict__ bhh) {
    __shared__ float xs[32 * 65];
    __shared__ float Ws[128 * 64];
    const int tid = threadIdx.x, t = blockIdx.y, n0 = blockIdx.x * 128;
    for (int i = tid; i < 32 * 64; i += 256) {
        int b = i >> 6, k = i & 63;
        xs[b * 65 + k] = x[((size_t)b * TT + t) * NIN + k];
    }
    for (int i = tid; i < 128 * 64; i += 256) {
        int r = i >> 6, k = i & 63;
        Ws[i] = Wih[(size_t)(n0 + r) * NIN + k];
    }
    __syncthreads();
    const int b = tid & 31, ng = tid >> 5;
    u64 acc[16];
#pragma unroll
    for (int m = 0; m < 16; ++m) acc[m] = 0ull;
    for (int k = 0; k < 64; k += 4) {
        u64 hp01 = pack2(xs[b * 65 + k], xs[b * 65 + k + 1]);
        u64 hp23 = pack2(xs[b * 65 + k + 2], xs[b * 65 + k + 3]);
#pragma unroll
        for (int m = 0; m < 16; ++m) {
            ulonglong2 wp = *(const ulonglong2*)&Ws[(ng * 16 + m) * 64 + k];
            acc[m] = ffma2(wp.x, hp01, acc[m]);
            acc[m] = ffma2(wp.y, hp23, acc[m]);
        }
    }
    size_t tg = (size_t)t * GB;
#pragma unroll
    for (int m = 0; m < 16; ++m) {
        int n = n0 + ng * 16 + m;
        float lo, hi; unpack2(acc[m], lo, hi);
        g_xg0[tg + (size_t)n * BB + b] = lo + hi + bih[n] + bhh[n];
    }
}

// ================= K2: xg1 = h0 @ W_ih1^T + biases =================
__global__ void __launch_bounds__(256) k_xg1(const float* __restrict__ Wih,
                                             const float* __restrict__ bih,
                                             const float* __restrict__ bhh) {
    __shared__ float hs[64 * 32];
    __shared__ float Ws[64 * 64];
    const int tid = threadIdx.x, t = blockIdx.y, n0 = blockIdx.x * 64;
    const int b = tid & 31, ng = tid >> 5;
    u64 acc[8];
#pragma unroll
    for (int m = 0; m < 8; ++m) acc[m] = 0ull;
    for (int kc = 0; kc < HH; kc += 64) {
        for (int i = tid; i < 64 * 32; i += 256)
            hs[i] = g_h0[(size_t)t * HB + (size_t)kc * BB + i];
        for (int i = tid; i < 64 * 64; i += 256) {
            int r = i >> 6, k = i & 63;
            Ws[i] = Wih[(size_t)(n0 + r) * HH + kc + k];
        }
        __syncthreads();
        for (int k = 0; k < 64; k += 4) {
            u64 hp01 = pack2(hs[(k + 0) * 32 + b], hs[(k + 1) * 32 + b]);
            u64 hp23 = pack2(hs[(k + 2) * 32 + b], hs[(k + 3) * 32 + b]);
#pragma unroll
            for (int m = 0; m < 8; ++m) {
                ulonglong2 wp = *(const ulonglong2*)&Ws[(ng * 8 + m) * 64 + k];
                acc[m] = ffma2(wp.x, hp01, acc[m]);
                acc[m] = ffma2(wp.y, hp23, acc[m]);
            }
        }
        __syncthreads();
    }
    size_t tg = (size_t)t * GB;
#pragma unroll
    for (int m = 0; m < 8; ++m) {
        int n = n0 + ng * 8 + m;
        float lo, hi; unpack2(acc[m], lo, hi);
        g_xg1[tg + (size_t)n * BB + b] = lo + hi + bih[n] + bhh[n];
    }
}

// ================= K3: dx1[t][k][b] = sum_n dg1[t][n][b] * W_ih1[n][k] =================
__global__ void __launch_bounds__(256) k_dx1(const float* __restrict__ Wih) {
    __shared__ float dgs[64 * 32];
    __shared__ float Ws[64 * 64];
    const int tid = threadIdx.x, t = blockIdx.y, kt0 = blockIdx.x * 64;
    const int b = tid & 31, kg = tid >> 5;
    u64 acc[4];
#pragma unroll
    for (int m = 0; m < 4; ++m) acc[m] = 0ull;
    for (int nb = 0; nb < GG; nb += 64) {
        for (int i = tid; i < 64 * 32; i += 256)
            dgs[i] = g_xg1[(size_t)t * GB + (size_t)nb * BB + i];
        for (int i = tid; i < 64 * 64; i += 256) {
            int r = i >> 6, k = i & 63;
            Ws[i] = Wih[(size_t)(nb + r) * HH + kt0 + k];
        }
        __syncthreads();
        for (int n = 0; n < 64; ++n) {
            u64 dpp = pack2(dgs[n * 32 + b], dgs[n * 32 + b]);
            ulonglong2 wa = *(const ulonglong2*)&Ws[n * 64 + kg * 8];
            ulonglong2 wb = *(const ulonglong2*)&Ws[n * 64 + kg * 8 + 4];
            acc[0] = ffma2(wa.x, dpp, acc[0]);
            acc[1] = ffma2(wa.y, dpp, acc[1]);
            acc[2] = ffma2(wb.x, dpp, acc[2]);
            acc[3] = ffma2(wb.y, dpp, acc[3]);
        }
        __syncthreads();
    }
#pragma unroll
    for (int p = 0; p < 4; ++p) {
        float lo, hi; unpack2(acc[p], lo, hi);
        g_dx1[(size_t)t * HB + (size_t)(kt0 + kg * 8 + 2 * p) * BB + b] = lo;
        g_dx1[(size_t)t * HB + (size_t)(kt0 + kg * 8 + 2 * p + 1) * BB + b] = hi;
    }
}

// ================= K4: out[b][t][k] = sum_n dg0[t][n][b] * W_ih0[n][k], k<64 =================
__global__ void __launch_bounds__(256) k_dx(const float* __restrict__ Wih,
                                            float* __restrict__ out) {
    __shared__ float dgs[64 * 32];
    __shared__ float Ws[64 * 64];
    const int tid = threadIdx.x, t = blockIdx.x;
    const int b = tid & 31, kg = tid >> 5;
    u64 acc[4];
#pragma unroll
    for (int m = 0; m < 4; ++m) acc[m] = 0ull;
    for (int nb = 0; nb < GG; nb += 64) {
        for (int i = tid; i < 64 * 32; i += 256)
            dgs[i] = g_xg0[(size_t)t * GB + (size_t)nb * BB + i];
        for (int i = tid; i < 64 * 64; i += 256) {
            int r = i >> 6, k = i & 63;
            Ws[i] = Wih[(size_t)(nb + r) * NIN + k];
        }
        __syncthreads();
        for (int n = 0; n < 64; ++n) {
            u64 dpp = pack2(dgs[n * 32 + b], dgs[n * 32 + b]);
            ulonglong2 wa = *(const ulonglong2*)&Ws[n * 64 + kg * 8];
            ulonglong2 wb = *(const ulonglong2*)&Ws[n * 64 + kg * 8 + 4];
            acc[0] = ffma2(wa.x, dpp, acc[0]);
            acc[1] = ffma2(wa.y, dpp, acc[1]);
            acc[2] = ffma2(wb.x, dpp, acc[2]);
            acc[3] = ffma2(wb.y, dpp, acc[3]);
        }
        __syncthreads();
    }
#pragma unroll
    for (int p = 0; p < 4; ++p) {
        float lo, hi; unpack2(acc[p], lo, hi);
        out[((size_t)b * TT + t) * NIN + kg * 8 + 2 * p] = lo;
        out[((size_t)b * TT + t) * NIN + kg * 8 + 2 * p + 1] = hi;
    }
}

// ================= persistent LSTM forward (512 threads/CTA) =================
// CTA owns 4 h-columns (j0..j0+3) -> 16 gate rows.
// 16 warps = 2 row-groups (8 rows) x 8 k-eighths (64 k).
// h_{t-1} staged as u64 pairs with XOR swizzle -> conflict-free LDS.64 reads.
// smem: sW 32KB | shq 64KB | sred 16KB | sact 2KB = 114KB
#define FWD_SMEM ((8192 + 16384 + 4096 + 512) * 4)
__global__ void __launch_bounds__(512, 1) lstm_fwd_kernel(const float* __restrict__ Whh,
                                                          int layer) {
    extern __shared__ float smem[];
    float* sW = smem;                          // [16][512]
    u64* shq = (u64*)(smem + 8192);            // [32][256] u64, swizzled
    float* sred = smem + 8192 + 16384;         // [8][512]
    float* sact = sred + 4096;                 // [512]

    float* gates = layer ? g_xg1 : g_xg0;
    float* cbuf = layer ? g_c1 : g_c0;

    const int tid = threadIdx.x, j0 = blockIdx.x * 4;
    const int b = tid & 31, wid = tid >> 5;
    const int rg = wid & 1, kh = wid >> 1;     // 2 row-groups x 8 k-eighths
    const int q_rho = tid >> 5, q_bb = tid & 31;
    const int q_n = (q_rho >> 2) * HH + j0 + (q_rho & 3);

    for (int i = tid; i < 16 * 512; i += 512) {
        int r = i >> 9, k = i & 511;
        int n = (r >> 2) * HH + j0 + (r & 3);
        sW[i] = Whh[(size_t)n * HH + k];
    }
    unsigned gen0 = *((volatile unsigned*)&g_bar_gen);
    float creg = 0.f;
    __syncthreads();

    for (int t = 0; t < TT; ++t) {
        size_t tg = (size_t)t * GB;
        float pre_xg = gates[tg + (size_t)q_n * BB + q_bb];

        // stage h_{t-1} into swizzled u64 buffer shq[b][k2 ^ (b&15)]
        if (t == 0) {
#pragma unroll
            for (int r = 0; r < 16; ++r) shq[tid + r * 512] = 0ull;
        } else {
            const float* src = g_hT + (size_t)(t - 1) * HB;   // [b][j]
#pragma unroll
            for (int r = 0; r < 8; ++r) {
                int i4 = tid + r * 512;
                float4 v = *(const float4*)&src[i4 * 4];
                int bb = i4 >> 7;
                int k2 = (i4 & 127) * 2;
                int s = bb & 15;
                u64* dst = shq + bb * 256;
                dst[k2 ^ s] = pack2(v.x, v.y);
                dst[(k2 + 1) ^ s] = pack2(v.z, v.w);
            }
        }
        __syncthreads();

        // matmul: 8 rows (rg), 64 k (kh), lane b
        u64 acc[8];
#pragma unroll
        for (int m = 0; m < 8; ++m) acc[m] = 0ull;
        const int s = b & 15;
        const u64* hq = shq + b * 256;
        const float* wp = sW + (rg * 8) * 512;
        const int kb = kh * 64;
#pragma unroll 4
        for (int k = kb; k < kb + 64; k += 4) {
            int k2 = k >> 1;
            u64 h01 = hq[k2 ^ s];
            u64 h23 = hq[(k2 + 1) ^ s];
#pragma unroll
            for (int m = 0; m < 8; ++m) {
                ulonglong2 w = *(const ulonglong2*)&wp[m * 512 + k];
                acc[m] = ffma2(w.x, h01, acc[m]);
                acc[m] = ffma2(w.y, h23, acc[m]);
            }
        }
#pragma unroll
        for (int m = 0; m < 8; ++m) {
            float lo, hi; unpack2(acc[m], lo, hi);
            sred[kh * 512 + (rg * 8 + m) * 32 + b] = lo + hi;
        }
        __syncthreads();

        // phase B: one gate value per thread
        {
            float g = pre_xg;
#pragma unroll
            for (int p = 0; p < 8; ++p) g += sred[p * 512 + tid];
            float v = (q_rho >= 8 && q_rho < 12) ? tanhf(g) : sigf(g);
            sact[tid] = v;
            gates[tg + (size_t)q_n * BB + q_bb] = v;
        }
        __syncthreads();

        // phase C: c/h update (tid<128)
        if (tid < 128) {
            int jl = tid >> 5, bb = tid & 31;
            float iv = sact[(0 + jl) * 32 + bb];
            float fv = sact[(4 + jl) * 32 + bb];
            float gv = sact[(8 + jl) * 32 + bb];
            float ov = sact[(12 + jl) * 32 + bb];
            float c = fv * creg + iv * gv;
            creg = c;
            float h = ov * tanhf(c);
            int j = j0 + jl;
            cbuf[(size_t)t * HB + (size_t)j * BB + bb] = c;
            g_hT[(size_t)t * HB + (size_t)bb * HH + j] = h;
            if (layer == 0)
                g_h0[(size_t)t * HB + (size_t)j * BB + bb] = h;
        }
        grid_barrier(gen0 + (unsigned)(t + 1));
    }
}

// ================= persistent LSTM backward (512 threads/CTA) =================
// CTA owns 16 j x 8 b. W_hh column slice 128KB resident in smem; dg staged 64KB/step.
// smem: sWc[2048][16] 128KB | sdg[2048][8] 64KB | sred[16][128] 8KB = 200KB
#define BWD_SMEM ((2048 * 16 + 2048 * 8 + 2048) * 4)
__global__ void __launch_bounds__(512, 1) lstm_bwd_kernel(const float* __restrict__ Whh,
                                                          const float* __restrict__ Wout,
                                                          int layer) {
    extern __shared__ float smem[];
    float* sWc = smem;                    // [n][16 j]
    float* sdg = smem + 2048 * 16;        // [n][8 b]
    float* sred = sdg + 2048 * 8;         // [16 warps][16 j * 8 b]

    float* gates = layer ? g_xg1 : g_xg0;
    const float* cbuf = layer ? g_c1 : g_c0;

    const int tid = threadIdx.x;
    const int j0 = (blockIdx.x >> 2) * 16;
    const int b0 = (blockIdx.x & 3) * 8;
    const int wid = tid >> 5, lane = tid & 31;
    const int bL = lane & 7, jh = lane >> 3;        // lane: 8 b x 4 j-quads
    const int cj = tid >> 3, cb = tid & 7;          // phase-C (tid<128): 16 j x 8 b

    // sWc[n][jj] = Whh[n][j0+jj]
    for (int i = tid; i < 2048 * 4; i += 512) {
        int n = i >> 2, q = i & 3;
        *(float4*)&sWc[n * 16 + q * 4] = *(const float4*)&Whh[(size_t)n * HH + j0 + q * 4];
    }
    unsigned gen0 = *((volatile unsigned*)&g_bar_gen);
    float dcreg = 0.f;
    float dho_c = 0.f;
    if (layer == 1 && tid < 128) dho_c = Wout[j0 + cj];
    __syncthreads();

    for (int t = TT - 1; t >= 0; --t) {
        // prefetch all barrier-independent operands (tid<128)
        float p_iv = 0.f, p_fv = 0.f, p_gv = 0.f, p_ov = 0.f;
        float p_c = 0.f, p_cprev = 0.f, p_dho = 0.f;
        size_t gb = 0;
        if (tid < 128) {
            int j = j0 + cj, b = b0 + cb;
            gb = (size_t)t * GB + (size_t)j * BB + b;
            size_t co = (size_t)t * HB + (size_t)j * BB + b;
            p_iv = gates[gb];
            p_fv = gates[gb + (size_t)512 * BB];
            p_gv = gates[gb + (size_t)1024 * BB];
            p_ov = gates[gb + (size_t)1536 * BB];
            p_c = cbuf[co];
            p_cprev = (t > 0) ? cbuf[co - HB] : 0.f;
            p_dho = (layer == 1) ? dho_c : g_dx1[co];
        }

        u64 a01 = 0ull, a23 = 0ull;
        if (t < TT - 1) {
            // stage dg[t+1][n][b0..b0+7]: 4096 float4, 8 per thread
            const float* dgp = gates + (size_t)(t + 1) * GB;
#pragma unroll
            for (int r = 0; r < 8; ++r) {
                int i4 = tid + r * 512;
                int n = i4 >> 1, bq = i4 & 1;
                *(float4*)&sdg[n * 8 + bq * 4] =
                    *(const float4*)&dgp[(size_t)n * BB + b0 + bq * 4];
            }
            __syncthreads();
            const int nbeg = wid * 128;
#pragma unroll 8
            for (int n = nbeg; n < nbeg + 128; ++n) {
                float dgv = sdg[n * 8 + bL];
                u64 dpp = pack2(dgv, dgv);
                ulonglong2 w = *(const ulonglong2*)&sWc[n * 16 + jh * 4];
                a01 = ffma2(w.x, dpp, a01);
                a23 = ffma2(w.y, dpp, a23);
            }
        }
        {
            float lo, hi;
            unpack2(a01, lo, hi);
            sred[wid * 128 + (jh * 4 + 0) * 8 + bL] = lo;
            sred[wid * 128 + (jh * 4 + 1) * 8 + bL] = hi;
            unpack2(a23, lo, hi);
            sred[wid * 128 + (jh * 4 + 2) * 8 + bL] = lo;
            sred[wid * 128 + (jh * 4 + 3) * 8 + bL] = hi;
        }
        __syncthreads();

        if (tid < 128) {
            float dhrec = 0.f;
#pragma unroll
            for (int h = 0; h < 16; ++h) dhrec += sred[h * 128 + tid];
            float dh = p_dho + dhrec;
            float tc = tanhf(p_c);
            float dc = dcreg + dh * p_ov * (1.f - tc * tc);
            float dgi = (dc * p_gv) * p_iv * (1.f - p_iv);
            float dgf = (dc * p_cprev) * p_fv * (1.f - p_fv);
            float dgg = (dc * p_iv) * (1.f - p_gv * p_gv);
            float dgo = (dh * tc) * p_ov * (1.f - p_ov);
            dcreg = dc * p_fv;
            gates[gb] = dgi;
            gates[gb + (size_t)512 * BB] = dgf;
            gates[gb + (size_t)1024 * BB] = dgg;
            gates[gb + (size_t)1536 * BB] = dgo;
        }
        grid_barrier(gen0 + (unsigned)(TT - t));
    }
}

extern "C" void kernel_launch(void* const* d_in, const int* in_sizes, int n_in,
                              void* d_out, int out_size) {
    const float* x    = (const float*)d_in[0];
    const float* Wih0 = (const float*)d_in[1];
    const float* Whh0 = (const float*)d_in[2];
    const float* bih0 = (const float*)d_in[3];
    const float* bhh0 = (const float*)d_in[4];
    const float* Wih1 = (const float*)d_in[5];
    const float* Whh1 = (const float*)d_in[6];
    const float* bih1 = (const float*)d_in[7];
    const float* bhh1 = (const float*)d_in[8];
    const float* Wout = (const float*)d_in[9];
    float* out = (float*)d_out;

    cudaFuncSetAttribute(lstm_fwd_kernel, cudaFuncAttributeMaxDynamicSharedMemorySize, FWD_SMEM);
    cudaFuncSetAttribute(lstm_bwd_kernel, cudaFuncAttributeMaxDynamicSharedMemorySize, BWD_SMEM);

    k_xg0<<<dim3(16, 512), 256>>>(x, Wih0, bih0, bhh0);
    lstm_fwd_kernel<<<NB, 512, FWD_SMEM>>>(Whh0, 0);
    k_xg1<<<dim3(32, 512), 256>>>(Wih1, bih1, bhh1);
    lstm_fwd_kernel<<<NB, 512, FWD_SMEM>>>(Whh1, 1);
    lstm_bwd_kernel<<<NB, 512, BWD_SMEM>>>(Whh1, Wout, 1);
    k_dx1<<<dim3(8, 512), 256>>>(Wih1);
    lstm_bwd_kernel<<<NB, 512, BWD_SMEM>>>(Whh0, Wout, 0);
    k_dx<<<512, 256>>>(Wih0, out);
}

// round 17
// speedup vs baseline: 2.0289x; 1.1166x over previous
#include <cuda_runtime.h>
#include <math.h>

#define TT 512
#define BB 32
#define HH 512
#define GG 2048
#define NIN 64
#define NB 128
#define HB 16384   // HH*BB
#define GB 65536   // GG*BB

typedef unsigned long long u64;

// ---- static device scratch ----
__device__ float g_xg0[(size_t)TT * GB];   // xg0 -> act0 -> dg0 (in place)
__device__ float g_xg1[(size_t)TT * GB];   // act1 -> dg1 (in place; written by fwd_pipe B)
__device__ float g_c0[(size_t)TT * HB];
__device__ float g_c1[(size_t)TT * HB];
__device__ float g_hT0[(size_t)TT * HB];   // [t][b][j] layer0 h
__device__ float g_hT1[(size_t)TT * HB];   // [t][b][j] layer1 h
__device__ float g_dx1[(size_t)TT * HB];   // [t][j][b]

__device__ unsigned g_bar_count = 0;
__device__ unsigned g_bar_gen   = 0;

__device__ __forceinline__ void grid_barrier(unsigned target) {
    __syncthreads();
    if (threadIdx.x == 0) {
        __threadfence();
        unsigned old = atomicAdd(&g_bar_count, 1u);
        if (old == NB - 1) {
            g_bar_count = 0;
            __threadfence();
            atomicExch(&g_bar_gen, target);
        } else {
            while ((int)(*(volatile unsigned*)&g_bar_gen - target) < 0) {}
            __threadfence();
        }
    }
    __syncthreads();
}

__device__ __forceinline__ float sigf(float x) { return 1.0f / (1.0f + expf(-x)); }
__device__ __forceinline__ u64 pack2(float x, float y) {
    u64 r; asm("mov.b64 %0, {%1, %2};" : "=l"(r) : "f"(x), "f"(y)); return r;
}
__device__ __forceinline__ void unpack2(u64 v, float& x, float& y) {
    asm("mov.b64 {%0, %1}, %2;" : "=f"(x), "=f"(y) : "l"(v));
}
__device__ __forceinline__ u64 ffma2(u64 a, u64 b, u64 c) {
    u64 d; asm("fma.rn.f32x2 %0, %1, %2, %3;" : "=l"(d) : "l"(a), "l"(b), "l"(c)); return d;
}

// ================= K1: xg0 = x @ W_ih0^T + b_ih0 + b_hh0, layout [t][n][b] =================
__global__ void __launch_bounds__(256) k_xg0(const float* __restrict__ x,
                                             const float* __restrict__ Wih,
                                             const float* __restrict__ bih,
                                             const float* __restrict__ bhh) {
    __shared__ float xs[32 * 65];
    __shared__ float Ws[128 * 64];
    const int tid = threadIdx.x, t = blockIdx.y, n0 = blockIdx.x * 128;
    for (int i = tid; i < 32 * 64; i += 256) {
        int b = i >> 6, k = i & 63;
        xs[b * 65 + k] = x[((size_t)b * TT + t) * NIN + k];
    }
    for (int i = tid; i < 128 * 64; i += 256) {
        int r = i >> 6, k = i & 63;
        Ws[i] = Wih[(size_t)(n0 + r) * NIN + k];
    }
    __syncthreads();
    const int b = tid & 31, ng = tid >> 5;
    u64 acc[16];
#pragma unroll
    for (int m = 0; m < 16; ++m) acc[m] = 0ull;
    for (int k = 0; k < 64; k += 4) {
        u64 hp01 = pack2(xs[b * 65 + k], xs[b * 65 + k + 1]);
        u64 hp23 = pack2(xs[b * 65 + k + 2], xs[b * 65 + k + 3]);
#pragma unroll
        for (int m = 0; m < 16; ++m) {
            ulonglong2 wp = *(const ulonglong2*)&Ws[(ng * 16 + m) * 64 + k];
            acc[m] = ffma2(wp.x, hp01, acc[m]);
            acc[m] = ffma2(wp.y, hp23, acc[m]);
        }
    }
    size_t tg = (size_t)t * GB;
#pragma unroll
    for (int m = 0; m < 16; ++m) {
        int n = n0 + ng * 16 + m;
        float lo, hi; unpack2(acc[m], lo, hi);
        g_xg0[tg + (size_t)n * BB + b] = lo + hi + bih[n] + bhh[n];
    }
}

// ================= K4: out[b][t][k] = sum_n dg0[t][n][b] * W_ih0[n][k], k<64 =================
__global__ void __launch_bounds__(256) k_dx(const float* __restrict__ Wih,
                                            float* __restrict__ out) {
    __shared__ float dgs[64 * 32];
    __shared__ float Ws[64 * 64];
    const int tid = threadIdx.x, t = blockIdx.x;
    const int b = tid & 31, kg = tid >> 5;
    u64 acc[4];
#pragma unroll
    for (int m = 0; m < 4; ++m) acc[m] = 0ull;
    for (int nb = 0; nb < GG; nb += 64) {
        for (int i = tid; i < 64 * 32; i += 256)
            dgs[i] = g_xg0[(size_t)t * GB + (size_t)nb * BB + i];
        for (int i = tid; i < 64 * 64; i += 256) {
            int r = i >> 6, k = i & 63;
            Ws[i] = Wih[(size_t)(nb + r) * NIN + k];
        }
        __syncthreads();
        for (int n = 0; n < 64; ++n) {
            u64 dpp = pack2(dgs[n * 32 + b], dgs[n * 32 + b]);
            ulonglong2 wa = *(const ulonglong2*)&Ws[n * 64 + kg * 8];
            ulonglong2 wb = *(const ulonglong2*)&Ws[n * 64 + kg * 8 + 4];
            acc[0] = ffma2(wa.x, dpp, acc[0]);
            acc[1] = ffma2(wa.y, dpp, acc[1]);
            acc[2] = ffma2(wb.x, dpp, acc[2]);
            acc[3] = ffma2(wb.y, dpp, acc[3]);
        }
        __syncthreads();
    }
#pragma unroll
    for (int p = 0; p < 4; ++p) {
        float lo, hi; unpack2(acc[p], lo, hi);
        out[((size_t)b * TT + t) * NIN + kg * 8 + 2 * p] = lo;
        out[((size_t)b * TT + t) * NIN + kg * 8 + 2 * p + 1] = hi;
    }
}

// ---------- shared helpers for pipelined kernels ----------
// stage h[t] ([b][j], 32x512 floats) into swizzled u64 buffer shq[b][k2 ^ (b&15)]
__device__ __forceinline__ void stage_h(u64* shq, const float* src, int tid) {
    if (!src) {
#pragma unroll
        for (int r = 0; r < 16; ++r) shq[tid + r * 512] = 0ull;
    } else {
#pragma unroll
        for (int r = 0; r < 8; ++r) {
            int i4 = tid + r * 512;
            float4 v = *(const float4*)&src[i4 * 4];
            int bb = i4 >> 7;
            int k2 = (i4 & 127) * 2;
            int s = bb & 15;
            u64* dst = shq + bb * 256;
            dst[k2 ^ s] = pack2(v.x, v.y);
            dst[(k2 + 1) ^ s] = pack2(v.z, v.w);
        }
    }
}

// 32 gate-rows x 32 b x 512 k matmul: warp = (rg: 8 rows) x (kq: 128 k)
__device__ __forceinline__ void mm32(const float* sW, const u64* shq, float* sred,
                                     int rg, int kq, int b, bool accum) {
    u64 acc[8];
#pragma unroll
    for (int m = 0; m < 8; ++m) acc[m] = 0ull;
    const int sx = b & 15;
    const u64* hq = shq + b * 256;
    const float* wp = sW + (rg * 8) * 512;
    const int kb = kq * 128;
#pragma unroll 4
    for (int k = kb; k < kb + 128; k += 4) {
        int k2 = k >> 1;
        u64 h01 = hq[k2 ^ sx];
        u64 h23 = hq[(k2 + 1) ^ sx];
#pragma unroll
        for (int m = 0; m < 8; ++m) {
            ulonglong2 w = *(const ulonglong2*)&wp[m * 512 + k];
            acc[m] = ffma2(w.x, h01, acc[m]);
            acc[m] = ffma2(w.y, h23, acc[m]);
        }
    }
#pragma unroll
    for (int m = 0; m < 8; ++m) {
        float lo, hi; unpack2(acc[m], lo, hi);
        int idx = kq * 1024 + (rg * 8 + m) * 32 + b;
        sred[idx] = accum ? sred[idx] + (lo + hi) : (lo + hi);
    }
}

// ================= pipelined forward: A(0..63)=L0 at t=s, B(64..127)=L1 at t=s-1 =================
// smem floats: sWa 16384 | sWb 16384 | shq 16384 | sred 4096 | sact 1024 = 54272 (212KB)
#define FWDP_SMEM (54272 * 4)
__global__ void __launch_bounds__(512, 1) fwd_pipe(const float* __restrict__ Whh0,
                                                   const float* __restrict__ Wih1,
                                                   const float* __restrict__ Whh1,
                                                   const float* __restrict__ bih1,
                                                   const float* __restrict__ bhh1) {
    extern __shared__ float sm[];
    float* sWa = sm;
    float* sWb = sm + 16384;
    u64*   shq = (u64*)(sm + 32768);
    float* sred = sm + 32768 + 16384;
    float* sact = sred + 4096;

    const int tid = threadIdx.x;
    const bool isB = blockIdx.x >= 64;
    const int j0 = (isB ? (int)blockIdx.x - 64 : (int)blockIdx.x) * 8;
    const int b = tid & 31, wid = tid >> 5;
    const int rg = wid & 3, kq = wid >> 2;
    const int rho0 = tid >> 5, rho1 = (tid >> 5) + 16;
    const int n0 = (rho0 >> 3) * HH + j0 + (rho0 & 7);
    const int n1 = (rho1 >> 3) * HH + j0 + (rho1 & 7);

    for (int i = tid; i < 32 * 512; i += 512) {
        int rho = i >> 9, k = i & 511;
        int n = (rho >> 3) * HH + j0 + (rho & 7);
        if (!isB) sWa[i] = Whh0[(size_t)n * HH + k];
        else {
            sWa[i] = Wih1[(size_t)n * HH + k];
            sWb[i] = Whh1[(size_t)n * HH + k];
        }
    }
    float bias0 = 0.f, bias1 = 0.f;
    if (isB) { bias0 = bih1[n0] + bhh1[n0]; bias1 = bih1[n1] + bhh1[n1]; }

    unsigned gen0 = *((volatile unsigned*)&g_bar_gen);
    float creg = 0.f;
    __syncthreads();

    for (int s = 0; s <= 512; ++s) {
        if (!isB) {
            if (s < 512) {
                const int t = s;
                size_t tg = (size_t)t * GB;
                float px0 = g_xg0[tg + (size_t)n0 * BB + b];
                float px1 = g_xg0[tg + (size_t)n1 * BB + b];
                stage_h(shq, t == 0 ? (const float*)0 : g_hT0 + (size_t)(t - 1) * HB, tid);
                __syncthreads();
                mm32(sWa, shq, sred, rg, kq, b, false);
                __syncthreads();
                // phase B: q0=tid, q1=tid+512
                {
                    float g0 = sred[tid] + sred[1024 + tid] + sred[2048 + tid] + sred[3072 + tid] + px0;
                    float g1 = sred[512 + tid] + sred[1536 + tid] + sred[2560 + tid] + sred[3584 + tid] + px1;
                    float v0 = (rho0 >= 16 && rho0 < 24) ? tanhf(g0) : sigf(g0);
                    float v1 = (rho1 >= 16 && rho1 < 24) ? tanhf(g1) : sigf(g1);
                    sact[tid] = v0; sact[tid + 512] = v1;
                    g_xg0[tg + (size_t)n0 * BB + b] = v0;
                    g_xg0[tg + (size_t)n1 * BB + b] = v1;
                }
                __syncthreads();
                if (tid < 256) {
                    int jl = tid >> 5, bb = tid & 31;
                    float iv = sact[jl * 32 + bb];
                    float fv = sact[(8 + jl) * 32 + bb];
                    float gv = sact[(16 + jl) * 32 + bb];
                    float ov = sact[(24 + jl) * 32 + bb];
                    float c = fv * creg + iv * gv;
                    creg = c;
                    g_c0[(size_t)t * HB + (size_t)(j0 + jl) * BB + bb] = c;
                    g_hT0[(size_t)t * HB + (size_t)bb * HH + (j0 + jl)] = ov * tanhf(c);
                }
            }
        } else {
            if (s >= 1) {
                const int t = s - 1;
                size_t tg = (size_t)t * GB;
                stage_h(shq, g_hT0 + (size_t)t * HB, tid);
                __syncthreads();
                mm32(sWa, shq, sred, rg, kq, b, false);   // xg1 part
                __syncthreads();
                stage_h(shq, t == 0 ? (const float*)0 : g_hT1 + (size_t)(t - 1) * HB, tid);
                __syncthreads();
                mm32(sWb, shq, sred, rg, kq, b, true);    // recurrent part
                __syncthreads();
                {
                    float g0 = sred[tid] + sred[1024 + tid] + sred[2048 + tid] + sred[3072 + tid] + bias0;
                    float g1 = sred[512 + tid] + sred[1536 + tid] + sred[2560 + tid] + sred[3584 + tid] + bias1;
                    float v0 = (rho0 >= 16 && rho0 < 24) ? tanhf(g0) : sigf(g0);
                    float v1 = (rho1 >= 16 && rho1 < 24) ? tanhf(g1) : sigf(g1);
                    sact[tid] = v0; sact[tid + 512] = v1;
                    g_xg1[tg + (size_t)n0 * BB + b] = v0;
                    g_xg1[tg + (size_t)n1 * BB + b] = v1;
                }
                __syncthreads();
                if (tid < 256) {
                    int jl = tid >> 5, bb = tid & 31;
                    float iv = sact[jl * 32 + bb];
                    float fv = sact[(8 + jl) * 32 + bb];
                    float gv = sact[(16 + jl) * 32 + bb];
                    float ov = sact[(24 + jl) * 32 + bb];
                    float c = fv * creg + iv * gv;
                    creg = c;
                    g_c1[(size_t)t * HB + (size_t)(j0 + jl) * BB + bb] = c;
                    g_hT1[(size_t)t * HB + (size_t)bb * HH + (j0 + jl)] = ov * tanhf(c);
                }
            }
        }
        grid_barrier(gen0 + (unsigned)(s + 1));
    }
}

// ================= pipelined backward =================
// A (0..63):  L1 bwd at t=511-s, tile 16j x 16b
// B1 (64..95): dx1 at t=512-s, tile 16k x 32b
// B2 (96..127): L0 bwd at t=513-s, tile 16j x 32b
// smem floats: sWcol 32768 (128KB) | sdg 16384 (64KB) | sred 8192 (32KB) = 57344 (224KB)
#define BWDP_SMEM (57344 * 4)
__global__ void __launch_bounds__(512, 1) bwd_pipe(const float* __restrict__ Whh0,
                                                   const float* __restrict__ Whh1,
                                                   const float* __restrict__ Wih1,
                                                   const float* __restrict__ Wout) {
    extern __shared__ float sm[];
    float* sWcol = sm;              // [2048][16]
    float* sdg   = sm + 32768;      // chunk buffer
    float* sred  = sm + 32768 + 16384;

    const int tid = threadIdx.x;
    const int blk = blockIdx.x;
    const int grp = (blk < 64) ? 0 : (blk < 96 ? 1 : 2);
    // weight column base j/k
    int jb0;
    const float* Wsrc;
    if (grp == 0) { jb0 = (blk >> 1) * 16; Wsrc = Whh1; }
    else if (grp == 1) { jb0 = (blk - 64) * 16; Wsrc = Wih1; }
    else { jb0 = (blk - 96) * 16; Wsrc = Whh0; }
    const int bA0 = (grp == 0) ? (blk & 1) * 16 : 0;

    for (int i = tid; i < 2048 * 4; i += 512) {
        int n = i >> 2, q = i & 3;
        *(float4*)&sWcol[n * 16 + q * 4] = *(const float4*)&Wsrc[(size_t)n * HH + jb0 + q * 4];
    }

    const int wid = tid >> 5, lane = tid & 31;
    // A matmul mapping
    const int a_bL = lane & 15, a_jh = lane >> 4;
    const int a_ns = wid & 7, a_jp = wid >> 3;
    const int a_jq = a_jp * 8 + a_jh * 4;
    // A phase-C mapping (tid<256)
    const int a_cj = tid >> 4, a_cb = tid & 15;
    float dho = 0.f;
    if (grp == 0 && tid < 256) dho = Wout[jb0 + a_cj];
    // B phase-C mapping
    const int c_k = tid >> 5, c_b = tid & 31;

    unsigned gen0 = *((volatile unsigned*)&g_bar_gen);
    float dcreg = 0.f;
    __syncthreads();

    for (int s = 0; s <= 513; ++s) {
        if (grp == 0) {
            if (s <= 511) {
                const int t = 511 - s;
                // prefetch pointwise operands
                float p_iv = 0.f, p_fv = 0.f, p_gv = 0.f, p_ov = 0.f, p_c = 0.f, p_cp = 0.f;
                size_t gb = 0;
                if (tid < 256) {
                    int j = jb0 + a_cj, bb = bA0 + a_cb;
                    gb = (size_t)t * GB + (size_t)j * BB + bb;
                    p_iv = g_xg1[gb];
                    p_fv = g_xg1[gb + (size_t)512 * BB];
                    p_gv = g_xg1[gb + (size_t)1024 * BB];
                    p_ov = g_xg1[gb + (size_t)1536 * BB];
                    size_t co = (size_t)t * HB + (size_t)j * BB + bb;
                    p_c = g_c1[co];
                    p_cp = (t > 0) ? g_c1[co - HB] : 0.f;
                }
                u64 a01 = 0ull, a23 = 0ull;
                if (t < 511) {
                    const float* dgp = g_xg1 + (size_t)(t + 1) * GB;
                    for (int c = 0; c < 2; ++c) {
                        const float* src = dgp + (size_t)(c * 1024) * BB;
#pragma unroll
                        for (int r = 0; r < 8; ++r) {
                            int i4 = tid + r * 512;
                            int nl = i4 >> 2, bq = (i4 & 3) * 4;
                            *(float4*)&sdg[nl * 16 + bq] = *(const float4*)&src[(size_t)nl * BB + bA0 + bq];
                        }
                        __syncthreads();
                        const float* wc = sWcol + (size_t)(c * 1024) * 16;
                        int nbeg = a_ns * 128;
#pragma unroll 4
                        for (int n = nbeg; n < nbeg + 128; ++n) {
                            float dgv = sdg[n * 16 + a_bL];
                            u64 dpp = pack2(dgv, dgv);
                            ulonglong2 w = *(const ulonglong2*)&wc[n * 16 + a_jq];
                            a01 = ffma2(w.x, dpp, a01);
                            a23 = ffma2(w.y, dpp, a23);
                        }
                        __syncthreads();
                    }
                }
                {
                    float lo, hi;
                    unpack2(a01, lo, hi);
                    sred[a_ns * 256 + (a_jq + 0) * 16 + a_bL] = lo;
                    sred[a_ns * 256 + (a_jq + 1) * 16 + a_bL] = hi;
                    unpack2(a23, lo, hi);
                    sred[a_ns * 256 + (a_jq + 2) * 16 + a_bL] = lo;
                    sred[a_ns * 256 + (a_jq + 3) * 16 + a_bL] = hi;
                }
                __syncthreads();
                if (tid < 256) {
                    float dhrec = 0.f;
#pragma unroll
                    for (int h = 0; h < 8; ++h) dhrec += sred[h * 256 + a_cj * 16 + a_cb];
                    float dh = dho + dhrec;
                    float tc = tanhf(p_c);
                    float dc = dcreg + dh * p_ov * (1.f - tc * tc);
                    float dgi = (dc * p_gv) * p_iv * (1.f - p_iv);
                    float dgf = (dc * p_cp) * p_fv * (1.f - p_fv);
                    float dgg = (dc * p_iv) * (1.f - p_gv * p_gv);
                    float dgo = (dh * tc) * p_ov * (1.f - p_ov);
                    dcreg = dc * p_fv;
                    g_xg1[gb] = dgi;
                    g_xg1[gb + (size_t)512 * BB] = dgf;
                    g_xg1[gb + (size_t)1024 * BB] = dgg;
                    g_xg1[gb + (size_t)1536 * BB] = dgo;
                }
                __syncthreads();   // sred reuse safety across steps
            }
        } else {
            // shared B matmul: 4 chunks x (512 n x 32 b) against sWcol -> 16 outputs (k or j)
            const int t = (grp == 1) ? (512 - s) : (513 - s);
            const bool active = (grp == 1) ? (s >= 1 && s <= 512) : (s >= 2);
            if (active) {
                // B2 prefetch pointwise operands
                float p_iv = 0.f, p_fv = 0.f, p_gv = 0.f, p_ov = 0.f, p_c = 0.f, p_cp = 0.f, p_dx = 0.f;
                size_t gb = 0;
                if (grp == 2) {
                    int j = jb0 + c_k, bb = c_b;
                    gb = (size_t)t * GB + (size_t)j * BB + bb;
                    p_iv = g_xg0[gb];
                    p_fv = g_xg0[gb + (size_t)512 * BB];
                    p_gv = g_xg0[gb + (size_t)1024 * BB];
                    p_ov = g_xg0[gb + (size_t)1536 * BB];
                    size_t co = (size_t)t * HB + (size_t)j * BB + bb;
                    p_c = g_c0[co];
                    p_cp = (t > 0) ? g_c0[co - HB] : 0.f;
                    p_dx = g_dx1[co];
                }
                u64 acc[8];
#pragma unroll
                for (int m = 0; m < 8; ++m) acc[m] = 0ull;
                const bool do_mm = (grp == 1) || (t < 511);
                if (do_mm) {
                    const float* dgp = (grp == 1) ? (g_xg1 + (size_t)t * GB)
                                                  : (g_xg0 + (size_t)(t + 1) * GB);
                    for (int c = 0; c < 4; ++c) {
                        const float* src = dgp + (size_t)(c * 512) * BB;
#pragma unroll
                        for (int r = 0; r < 8; ++r) {
                            int i4 = tid + r * 512;
                            int nl = i4 >> 3, bq = (i4 & 7) * 4;
                            *(float4*)&sdg[nl * 32 + bq] = *(const float4*)&src[(size_t)nl * BB + bq];
                        }
                        __syncthreads();
                        const float* wc = sWcol + (size_t)(c * 512) * 16;
                        int nbeg = wid * 32;
#pragma unroll 4
                        for (int n = nbeg; n < nbeg + 32; ++n) {
                            float dgv = sdg[n * 32 + lane];
                            u64 dpp = pack2(dgv, dgv);
                            const float* wr = wc + n * 16;
                            ulonglong2 wA = *(const ulonglong2*)&wr[0];
                            ulonglong2 wB = *(const ulonglong2*)&wr[4];
                            ulonglong2 wC = *(const ulonglong2*)&wr[8];
                            ulonglong2 wD = *(const ulonglong2*)&wr[12];
                            acc[0] = ffma2(wA.x, dpp, acc[0]); acc[1] = ffma2(wA.y, dpp, acc[1]);
                            acc[2] = ffma2(wB.x, dpp, acc[2]); acc[3] = ffma2(wB.y, dpp, acc[3]);
                            acc[4] = ffma2(wC.x, dpp, acc[4]); acc[5] = ffma2(wC.y, dpp, acc[5]);
                            acc[6] = ffma2(wD.x, dpp, acc[6]); acc[7] = ffma2(wD.y, dpp, acc[7]);
                        }
                        __syncthreads();
                    }
                }
#pragma unroll
                for (int p = 0; p < 8; ++p) {
                    float lo, hi; unpack2(acc[p], lo, hi);
                    sred[wid * 512 + (2 * p) * 32 + lane] = lo;
                    sred[wid * 512 + (2 * p + 1) * 32 + lane] = hi;
                }
                __syncthreads();
                float tot = 0.f;
#pragma unroll
                for (int h = 0; h < 16; ++h) tot += sred[h * 512 + c_k * 32 + c_b];
                if (grp == 1) {
                    g_dx1[(size_t)t * HB + (size_t)(jb0 + c_k) * BB + c_b] = tot;
                } else {
                    float dh = p_dx + tot;
                    float tc = tanhf(p_c);
                    float dc = dcreg + dh * p_ov * (1.f - tc * tc);
                    float dgi = (dc * p_gv) * p_iv * (1.f - p_iv);
                    float dgf = (dc * p_cp) * p_fv * (1.f - p_fv);
                    float dgg = (dc * p_iv) * (1.f - p_gv * p_gv);
                    float dgo = (dh * tc) * p_ov * (1.f - p_ov);
                    dcreg = dc * p_fv;
                    g_xg0[gb] = dgi;
                    g_xg0[gb + (size_t)512 * BB] = dgf;
                    g_xg0[gb + (size_t)1024 * BB] = dgg;
                    g_xg0[gb + (size_t)1536 * BB] = dgo;
                }
                __syncthreads();   // sred reuse safety
            }
        }
        grid_barrier(gen0 + (unsigned)(s + 1));
    }
}

extern "C" void kernel_launch(void* const* d_in, const int* in_sizes, int n_in,
                              void* d_out, int out_size) {
    const float* x    = (const float*)d_in[0];
    const float* Wih0 = (const float*)d_in[1];
    const float* Whh0 = (const float*)d_in[2];
    const float* bih0 = (const float*)d_in[3];
    const float* bhh0 = (const float*)d_in[4];
    const float* Wih1 = (const float*)d_in[5];
    const float* Whh1 = (const float*)d_in[6];
    const float* bih1 = (const float*)d_in[7];
    const float* bhh1 = (const float*)d_in[8];
    const float* Wout = (const float*)d_in[9];
    float* out = (float*)d_out;

    cudaFuncSetAttribute(fwd_pipe, cudaFuncAttributeMaxDynamicSharedMemorySize, FWDP_SMEM);
    cudaFuncSetAttribute(bwd_pipe, cudaFuncAttributeMaxDynamicSharedMemorySize, BWDP_SMEM);

    k_xg0<<<dim3(16, 512), 256>>>(x, Wih0, bih0, bhh0);
    fwd_pipe<<<NB, 512, FWDP_SMEM>>>(Whh0, Wih1, Whh1, bih1, bhh1);
    bwd_pipe<<<NB, 512, BWDP_SMEM>>>(Whh0, Whh1, Wih1, Wout);
    k_dx<<<512, 256>>>(Wih0, out);
}